// round 14
// baseline (speedup 1.0000x reference)
#include <cuda_runtime.h>

#define N2    128
#define MREG  16384
#define START 6
#define RPB   128            // regions per block
#define TPB   512            // 4 roles x 128 regions
#define NBLK  (MREG / RPB)   // 128
#define T     16
#define NT    (N2 / T)       // 8
#define PAD   132

// smem floats: sSI[PAD] + sPred[RPB*PAD] + sF[RPB*PAD]
#define SMEM_FLOATS (PAD + 2 * RPB * PAD)
#define SMEM_BYTES  (SMEM_FLOATS * 4)

__device__ float        g_partials[NBLK];
__device__ unsigned int g_count = 0;

__device__ __forceinline__ void load16(float* d, const float* s) {
#pragma unroll
    for (int q = 0; q < 4; ++q)
        *reinterpret_cast<float4*>(d + 4*q) = *reinterpret_cast<const float4*>(s + 4*q);
}
__device__ __forceinline__ void load24(float* d, const float* s) {
#pragma unroll
    for (int q = 0; q < 6; ++q)
        *reinterpret_cast<float4*>(d + 4*q) = *reinterpret_cast<const float4*>(s + 4*q);
}
// acc[iq] += w[iq-jj+16] * pj[jj]
__device__ __forceinline__ void mac8x16(float* acc, const float* w, const float* pj) {
#pragma unroll
    for (int jj = 0; jj < 16; ++jj)
#pragma unroll
        for (int iq = 0; iq < 8; ++iq)
            acc[iq] = fmaf(w[iq - jj + 16], pj[jj], acc[iq]);
}

// fully-unrolled history matvec: CNT units, k ascending == J descending.
template<int CNT>
__device__ __forceinline__ void histmac(float* acc, const float* wrow,
                                        const float* predRow) {
#pragma unroll
    for (int k = 0; k < CNT; ++k) {
        float w[24];  load24(w,  wrow + 16 * k);
        float pj[16]; load16(pj, predRow + 16 * (CNT - 1 - k));
        mac8x16(acc, w, pj);
    }
}
__device__ __forceinline__ void hist_dispatch(int n, float* acc,
                                              const float* wrow,
                                              const float* predRow) {
    switch (n) {
        case 1: histmac<1>(acc, wrow, predRow); break;
        case 2: histmac<2>(acc, wrow, predRow); break;
        case 3: histmac<3>(acc, wrow, predRow); break;
        case 4: histmac<4>(acc, wrow, predRow); break;
        case 5: histmac<5>(acc, wrow, predRow); break;
        case 6: histmac<6>(acc, wrow, predRow); break;
        case 7: histmac<7>(acc, wrow, predRow); break;
        default: break;
    }
}

// named-barrier helpers (ids: 1 = producer handoff, 2 = producer phase-end,
// 4+t = "pred tile t stored" event)
__device__ __forceinline__ void bar_sync(int id, int cnt) {
    asm volatile("bar.sync %0, %1;" :: "r"(id), "r"(cnt) : "memory");
}
__device__ __forceinline__ void bar_arrive(int id, int cnt) {
    asm volatile("bar.arrive %0, %1;" :: "r"(id), "r"(cnt) : "memory");
}

__global__ void __launch_bounds__(TPB, 1) npi_fused(
    const float* __restrict__ rt,
    const float* __restrict__ gt,
    const float* __restrict__ SI,
    const float* __restrict__ f,
    const float* __restrict__ seed,
    float* __restrict__ out)
{
    extern __shared__ float sm[];
    float* sSI   = sm;                 // [PAD]
    float* sPred = sm + PAD;           // [RPB][PAD]
    float* sF    = sPred + RPB * PAD;  // [RPB][PAD] f_eff rows

    const int tid = threadIdx.x;
    const int g   = tid >> 7;          // role: 0=P0,1=P1,2=C0,3=C1
    const int rid = tid & (RPB - 1);
    const int h8  = (g & 1) ? 8 : 0;   // half offset within tile
    const int m   = blockIdx.x * RPB + rid;

    float* myPred = sPred + rid * PAD;
    float* myF    = sF + rid * PAD;

    // ---- staging: f coalesced by all roles, SI ------------------------------
    {
        const int k0 = g * 32;
#pragma unroll 8
        for (int k = k0; k < k0 + 32; ++k)
            myF[k] = (k < 2) ? 0.0f : f[k * MREG + m];   // f_eff
    }
    if (tid < N2) sSI[tid] = SI[tid];
    else if (tid < PAD) sSI[tid] = 0.0f;
    __syncthreads();

    float siL[T];          // producers
    float fL[T];           // consumers
    float loss = 0.f;

    if (g <= 1) {
#pragma unroll
        for (int d = 1; d < T; ++d) siL[d] = sSI[d];
    } else {
#pragma unroll
        for (int d = 2; d < T; ++d) fL[d] = myF[d];
    }

    if (g <= 1) {
        // =================== PRODUCER SIDE (threads 0..255) ==================
        if (g == 0) {
            // tile 0: seeds + triangular
            float rtt[T];
#pragma unroll
            for (int ii = START; ii < T; ++ii) rtt[ii] = rt[ii * MREG + m];
            float pt[T], s[T];
#pragma unroll
            for (int ii = 0; ii < START; ++ii) pt[ii] = seed[ii * MREG + m];
#pragma unroll
            for (int ii = START; ii < T; ++ii) s[ii] = 0.f;
#pragma unroll
            for (int jj = 0; jj < T; ++jj) {
                if (jj >= START) pt[jj] = rtt[jj] * s[jj];
#pragma unroll
                for (int ii = (jj + 1 > START ? jj + 1 : START); ii < T; ++ii)
                    s[ii] = fmaf(siL[ii - jj], pt[jj], s[ii]);
            }
#pragma unroll
            for (int q = 0; q < 4; ++q)
                *reinterpret_cast<float4*>(myPred + 4*q) =
                    make_float4(pt[4*q], pt[4*q+1], pt[4*q+2], pt[4*q+3]);
        }
        bar_sync(2, 256);        // producer phase-end (drains STS)
        bar_arrive(4 + 0, 512);  // event: tile 0 ready

#pragma unroll 1
        for (int I = 1; I < NT; ++I) {
            const int c = I * T;
            float rtt[8];
#pragma unroll
            for (int q = 0; q < 8; ++q)
                rtt[q] = rt[(c + h8 + q) * MREG + m];

            float acc[8] = {0,0,0,0,0,0,0,0};
            hist_dispatch(I, acc, sSI + h8, myPred);

            if (g == 0) {
                float pt[8];
#pragma unroll
                for (int jj = 0; jj < 8; ++jj) {
                    pt[jj] = rtt[jj] * acc[jj];
#pragma unroll
                    for (int iq = jj + 1; iq < 8; ++iq)
                        acc[iq] = fmaf(siL[iq - jj], pt[jj], acc[iq]);
                }
#pragma unroll
                for (int q = 0; q < 2; ++q)
                    *reinterpret_cast<float4*>(myPred + c + 4*q) =
                        make_float4(pt[4*q], pt[4*q+1], pt[4*q+2], pt[4*q+3]);
            }

            bar_sync(1, 256);    // P0 -> P1 handoff

            if (g == 1) {
                float ptL[8];
#pragma unroll
                for (int q = 0; q < 2; ++q)
                    *reinterpret_cast<float4*>(ptL + 4*q) =
                        *reinterpret_cast<const float4*>(myPred + c + 4*q);
#pragma unroll
                for (int jj = 0; jj < 8; ++jj)
#pragma unroll
                    for (int iq = 0; iq < 8; ++iq)
                        acc[iq] = fmaf(siL[iq + 8 - jj], ptL[jj], acc[iq]);
                float pt[8];
#pragma unroll
                for (int jj = 0; jj < 8; ++jj) {
                    pt[jj] = rtt[jj] * acc[jj];
#pragma unroll
                    for (int iq = jj + 1; iq < 8; ++iq)
                        acc[iq] = fmaf(siL[iq - jj], pt[jj], acc[iq]);
                }
#pragma unroll
                for (int q = 0; q < 2; ++q)
                    *reinterpret_cast<float4*>(myPred + c + 8 + 4*q) =
                        make_float4(pt[4*q], pt[4*q+1], pt[4*q+2], pt[4*q+3]);
            }

            bar_sync(2, 256);        // producer phase-end
            bar_arrive(4 + I, 512);  // event: tile I ready
        }
    } else {
        // =================== CONSUMER SIDE (threads 256..511) ================
#pragma unroll 1
        for (int IC = 0; IC < NT; ++IC) {
            const int c2 = IC * T;
            float gtt[8];                       // prefetch before the wait
#pragma unroll
            for (int q = 0; q < 8; ++q)
                gtt[q] = gt[(c2 + h8 + q) * MREG + m];

            bar_sync(4 + IC, 512);              // wait: tile IC ready

            float dacc[8] = {0,0,0,0,0,0,0,0};
            if (IC >= 1)
                hist_dispatch(IC, dacc, myF + h8, myPred);

            float pd[T];
            load16(pd, myPred + c2);
            if (h8 == 0) {
#pragma unroll
                for (int jj = 0; jj < T; ++jj)
#pragma unroll
                    for (int iq = 0; iq < 8; ++iq)
                        if (iq - jj >= 2)
                            dacc[iq] = fmaf(fL[iq - jj], pd[jj], dacc[iq]);
            } else {
#pragma unroll
                for (int jj = 0; jj < T; ++jj)
#pragma unroll
                    for (int iq = 0; iq < 8; ++iq)
                        if (8 + iq - jj >= 2 && 8 + iq - jj <= 15)
                            dacc[iq] = fmaf(fL[8 + iq - jj], pd[jj], dacc[iq]);
            }

#pragma unroll
            for (int iq = 0; iq < 8; ++iq) {
                const int i = c2 + h8 + iq;
                float dp = dacc[iq];
                if (i < START) dp = (i == 0) ? 1e-9f : 0.f;
                const float diff = dp - gtt[iq];
                loss = fmaf(diff, diff, loss);
            }
        }
    }
    __syncthreads();   // join before reduction

    // ---- deterministic fused reduction --------------------------------------
#pragma unroll
    for (int o = 16; o; o >>= 1)
        loss += __shfl_xor_sync(0xffffffffu, loss, o);
    __shared__ float warpsum[TPB / 32];
    __shared__ bool  s_last;
    if ((tid & 31) == 0) warpsum[tid >> 5] = loss;
    __syncthreads();
    if (tid == 0) {
        float s = 0.f;
#pragma unroll
        for (int w = 0; w < TPB / 32; ++w) s += warpsum[w];
        g_partials[blockIdx.x] = s;
        __threadfence();
        unsigned prev = atomicAdd(&g_count, 1u);
        s_last = (prev == NBLK - 1u);
    }
    __syncthreads();
    if (s_last && tid < 32) {
        float v = 0.f;
#pragma unroll
        for (int k = 0; k < NBLK / 32; ++k)
            v += g_partials[tid + k * 32];
#pragma unroll
        for (int o = 16; o; o >>= 1)
            v += __shfl_xor_sync(0xffffffffu, v, o);
        if (tid == 0) {
            out[0] = v * (1.0f / ((float)N2 * (float)MREG));
            g_count = 0;   // reset for graph replay
        }
    }
}

extern "C" void kernel_launch(void* const* d_in, const int* in_sizes, int n_in,
                              void* d_out, int out_size)
{
    const float* rt   = (const float*)d_in[0];
    const float* gt   = (const float*)d_in[1];
    const float* SI   = (const float*)d_in[2];
    const float* f    = (const float*)d_in[3];
    const float* seed = (const float*)d_in[4];

    static bool attr_set = false;
    if (!attr_set) {
        cudaFuncSetAttribute(npi_fused,
                             cudaFuncAttributeMaxDynamicSharedMemorySize,
                             SMEM_BYTES);
        attr_set = true;
    }

    npi_fused<<<NBLK, TPB, SMEM_BYTES>>>(rt, gt, SI, f, seed, (float*)d_out);
}

// round 15
// speedup vs baseline: 1.2538x; 1.2538x over previous
#include <cuda_runtime.h>

#define N2    128
#define MREG  16384
#define START 6
#define RPB   64             // regions per block
#define TPB   256            // 4 roles x 64 regions
#define NBLK  (MREG / RPB)   // 256
#define T     16
#define NT    (N2 / T)       // 8
#define PAD   132

// smem floats: sSI[PAD] + sPred[RPB*PAD] + sF[RPB*PAD]
#define SMEM_FLOATS (PAD + 2 * RPB * PAD)
#define SMEM_BYTES  (SMEM_FLOATS * 4)    // ~68 KB -> 2 blocks/SM fits 228 KB

__device__ float        g_partials[NBLK];
__device__ unsigned int g_count = 0;

__device__ __forceinline__ void load16(float* d, const float* s) {
#pragma unroll
    for (int q = 0; q < 4; ++q)
        *reinterpret_cast<float4*>(d + 4*q) = *reinterpret_cast<const float4*>(s + 4*q);
}
__device__ __forceinline__ void load24(float* d, const float* s) {
#pragma unroll
    for (int q = 0; q < 6; ++q)
        *reinterpret_cast<float4*>(d + 4*q) = *reinterpret_cast<const float4*>(s + 4*q);
}
// acc[iq] += w[iq-jj+16] * pj[jj]
__device__ __forceinline__ void mac8x16(float* acc, const float* w, const float* pj) {
#pragma unroll
    for (int jj = 0; jj < 16; ++jj)
#pragma unroll
        for (int iq = 0; iq < 8; ++iq)
            acc[iq] = fmaf(w[iq - jj + 16], pj[jj], acc[iq]);
}
// fully-unrolled history matvec: CNT units, k ascending == J descending
template<int CNT>
__device__ __forceinline__ void histmac(float* acc, const float* wrow,
                                        const float* predRow) {
#pragma unroll
    for (int k = 0; k < CNT; ++k) {
        float w[24];  load24(w,  wrow + 16 * k);
        float pj[16]; load16(pj, predRow + 16 * (CNT - 1 - k));
        mac8x16(acc, w, pj);
    }
}

__device__ __forceinline__ void bar_sync(int id, int cnt) {
    asm volatile("bar.sync %0, %1;" :: "r"(id), "r"(cnt) : "memory");
}

// ---- one pipeline phase, I compile-time --------------------------------
template<int I>
__device__ __forceinline__ void run_phase(
    int g, int h8, int m,
    float* myPred, const float* myF, const float* sSI_,
    const float* siL, const float* fL,
    const float* __restrict__ rt, const float* __restrict__ gt,
    float& loss)
{
    if (g < 2) {
        if constexpr (I < NT) {
            constexpr int c = I * T;
            float rtt[8];
#pragma unroll
            for (int q = 0; q < 8; ++q)
                rtt[q] = rt[(c + h8 + q) * MREG + m];

            float acc[8] = {0,0,0,0,0,0,0,0};
            histmac<I>(acc, sSI_ + h8, myPred);

            if (g == 0) {
                float pt[8];
#pragma unroll
                for (int jj = 0; jj < 8; ++jj) {
                    pt[jj] = rtt[jj] * acc[jj];
#pragma unroll
                    for (int iq = jj + 1; iq < 8; ++iq)
                        acc[iq] = fmaf(siL[iq - jj], pt[jj], acc[iq]);
                }
#pragma unroll
                for (int q = 0; q < 2; ++q)
                    *reinterpret_cast<float4*>(myPred + c + 4*q) =
                        make_float4(pt[4*q], pt[4*q+1], pt[4*q+2], pt[4*q+3]);
            }

            bar_sync(1, 128);          // P0 -> P1 handoff (producers only)

            if (g == 1) {
                float ptL[8];
#pragma unroll
                for (int q = 0; q < 2; ++q)
                    *reinterpret_cast<float4*>(ptL + 4*q) =
                        *reinterpret_cast<const float4*>(myPred + c + 4*q);
#pragma unroll
                for (int jj = 0; jj < 8; ++jj)
#pragma unroll
                    for (int iq = 0; iq < 8; ++iq)
                        acc[iq] = fmaf(siL[iq + 8 - jj], ptL[jj], acc[iq]);
                float pt[8];
#pragma unroll
                for (int jj = 0; jj < 8; ++jj) {
                    pt[jj] = rtt[jj] * acc[jj];
#pragma unroll
                    for (int iq = jj + 1; iq < 8; ++iq)
                        acc[iq] = fmaf(siL[iq - jj], pt[jj], acc[iq]);
                }
#pragma unroll
                for (int q = 0; q < 2; ++q)
                    *reinterpret_cast<float4*>(myPred + c + 8 + 4*q) =
                        make_float4(pt[4*q], pt[4*q+1], pt[4*q+2], pt[4*q+3]);
            }
        }
    } else {
        // consumers: output tile IC = I-1
        constexpr int IC = I - 1;
        constexpr int c2 = IC * T;
        float gtt[8];
#pragma unroll
        for (int q = 0; q < 8; ++q)
            gtt[q] = gt[(c2 + h8 + q) * MREG + m];

        float dacc[8] = {0,0,0,0,0,0,0,0};
        if constexpr (IC >= 1)
            histmac<IC>(dacc, myF + h8, myPred);

        float pd[T];
        load16(pd, myPred + c2);
        if (h8 == 0) {
#pragma unroll
            for (int jj = 0; jj < T; ++jj)
#pragma unroll
                for (int iq = 0; iq < 8; ++iq)
                    if (iq - jj >= 2)
                        dacc[iq] = fmaf(fL[iq - jj], pd[jj], dacc[iq]);
        } else {
#pragma unroll
            for (int jj = 0; jj < T; ++jj)
#pragma unroll
                for (int iq = 0; iq < 8; ++iq)
                    if (8 + iq - jj >= 2 && 8 + iq - jj <= 15)
                        dacc[iq] = fmaf(fL[8 + iq - jj], pd[jj], dacc[iq]);
        }

#pragma unroll
        for (int iq = 0; iq < 8; ++iq) {
            const int i = c2 + h8 + iq;
            float dp = dacc[iq];
            if (i < START) dp = (i == 0) ? 1e-9f : 0.f;
            const float diff = dp - gtt[iq];
            loss = fmaf(diff, diff, loss);
        }
    }
    __syncthreads();   // phase end: tile I published
}

template<int I>
__device__ __forceinline__ void run_phases(
    int g, int h8, int m,
    float* myPred, const float* myF, const float* sSI_,
    const float* siL, const float* fL,
    const float* __restrict__ rt, const float* __restrict__ gt,
    float& loss)
{
    if constexpr (I <= NT) {
        run_phase<I>(g, h8, m, myPred, myF, sSI_, siL, fL, rt, gt, loss);
        run_phases<I + 1>(g, h8, m, myPred, myF, sSI_, siL, fL, rt, gt, loss);
    }
}

__global__ void __launch_bounds__(TPB, 2) npi_fused(
    const float* __restrict__ rt,
    const float* __restrict__ gt,
    const float* __restrict__ SI,
    const float* __restrict__ f,
    const float* __restrict__ seed,
    float* __restrict__ out)
{
    extern __shared__ float sm[];
    float* sSI   = sm;                 // [PAD]
    float* sPred = sm + PAD;           // [RPB][PAD]
    float* sF    = sPred + RPB * PAD;  // [RPB][PAD] f_eff rows

    const int tid = threadIdx.x;
    const int g   = tid >> 6;          // role: 0=P0,1=P1,2=C0,3=C1 (64 thr each)
    const int rid = tid & (RPB - 1);
    const int h8  = (g & 1) ? 8 : 0;
    const int m   = blockIdx.x * RPB + rid;

    float* myPred = sPred + rid * PAD;
    float* myF    = sF + rid * PAD;

    // ---- staging: f coalesced (role g loads lags g*32..g*32+31), SI ---------
    {
        const int k0 = g * 32;
#pragma unroll 8
        for (int k = k0; k < k0 + 32; ++k)
            myF[k] = (k < 2) ? 0.0f : f[k * MREG + m];   // f_eff
    }
    if (tid < N2) sSI[tid] = SI[tid];
    else if (tid < PAD) sSI[tid] = 0.0f;
    __syncthreads();

    float siL[T];          // producers
    float fL[T];           // consumers
    float loss = 0.f;

    if (g <= 1) {
#pragma unroll
        for (int d = 1; d < T; ++d) siL[d] = sSI[d];
    } else {
#pragma unroll
        for (int d = 2; d < T; ++d) fL[d] = myF[d];
    }

    // ---- tile 0: P0 computes full seed tile ---------------------------------
    if (g == 0) {
        float rtt[T];
#pragma unroll
        for (int ii = START; ii < T; ++ii) rtt[ii] = rt[ii * MREG + m];
        float pt[T], s[T];
#pragma unroll
        for (int ii = 0; ii < START; ++ii) pt[ii] = seed[ii * MREG + m];
#pragma unroll
        for (int ii = START; ii < T; ++ii) s[ii] = 0.f;
#pragma unroll
        for (int jj = 0; jj < T; ++jj) {
            if (jj >= START) pt[jj] = rtt[jj] * s[jj];
#pragma unroll
            for (int ii = (jj + 1 > START ? jj + 1 : START); ii < T; ++ii)
                s[ii] = fmaf(siL[ii - jj], pt[jj], s[ii]);
        }
#pragma unroll
        for (int q = 0; q < 4; ++q)
            *reinterpret_cast<float4*>(myPred + 4*q) =
                make_float4(pt[4*q], pt[4*q+1], pt[4*q+2], pt[4*q+3]);
    }
    __syncthreads();

    // ---- fully unrolled pipelined phases ------------------------------------
    run_phases<1>(g, h8, m, myPred, myF, sSI, siL, fL, rt, gt, loss);

    // ---- deterministic fused reduction --------------------------------------
#pragma unroll
    for (int o = 16; o; o >>= 1)
        loss += __shfl_xor_sync(0xffffffffu, loss, o);
    __shared__ float warpsum[TPB / 32];
    __shared__ bool  s_last;
    if ((tid & 31) == 0) warpsum[tid >> 5] = loss;
    __syncthreads();
    if (tid == 0) {
        float s = 0.f;
#pragma unroll
        for (int w = 0; w < TPB / 32; ++w) s += warpsum[w];
        g_partials[blockIdx.x] = s;
        __threadfence();
        unsigned prev = atomicAdd(&g_count, 1u);
        s_last = (prev == NBLK - 1u);
    }
    __syncthreads();
    if (s_last && tid < 32) {
        float v = 0.f;
#pragma unroll
        for (int k = 0; k < NBLK / 32; ++k)
            v += g_partials[tid + k * 32];
#pragma unroll
        for (int o = 16; o; o >>= 1)
            v += __shfl_xor_sync(0xffffffffu, v, o);
        if (tid == 0) {
            out[0] = v * (1.0f / ((float)N2 * (float)MREG));
            g_count = 0;   // reset for graph replay
        }
    }
}

extern "C" void kernel_launch(void* const* d_in, const int* in_sizes, int n_in,
                              void* d_out, int out_size)
{
    const float* rt   = (const float*)d_in[0];
    const float* gt   = (const float*)d_in[1];
    const float* SI   = (const float*)d_in[2];
    const float* f    = (const float*)d_in[3];
    const float* seed = (const float*)d_in[4];

    static bool attr_set = false;
    if (!attr_set) {
        cudaFuncSetAttribute(npi_fused,
                             cudaFuncAttributeMaxDynamicSharedMemorySize,
                             SMEM_BYTES);
        attr_set = true;
    }

    npi_fused<<<NBLK, TPB, SMEM_BYTES>>>(rt, gt, SI, f, seed, (float*)d_out);
}

// round 16
// speedup vs baseline: 1.3904x; 1.1089x over previous
#include <cuda_runtime.h>

#define N2    128
#define MREG  16384
#define START 6
#define RPB   128            // regions per block
#define TPB   512            // 4 roles x 128 regions
#define NBLK  (MREG / RPB)   // 128
#define T     16
#define NT    (N2 / T)       // 8
#define PAD   132

// smem floats: sSI[PAD] + sPred[RPB*PAD] + sF[RPB*PAD]
#define SMEM_FLOATS (PAD + 2 * RPB * PAD)
#define SMEM_BYTES  (SMEM_FLOATS * 4)

__device__ float        g_partials[NBLK];
__device__ unsigned int g_count = 0;

__device__ __forceinline__ void load16(float* d, const float* s) {
#pragma unroll
    for (int q = 0; q < 4; ++q)
        *reinterpret_cast<float4*>(d + 4*q) = *reinterpret_cast<const float4*>(s + 4*q);
}
__device__ __forceinline__ void load24(float* d, const float* s) {
#pragma unroll
    for (int q = 0; q < 6; ++q)
        *reinterpret_cast<float4*>(d + 4*q) = *reinterpret_cast<const float4*>(s + 4*q);
}
// acc[iq] += w[iq-jj+16] * pj[jj]
__device__ __forceinline__ void mac8x16(float* acc, const float* w, const float* pj) {
#pragma unroll
    for (int jj = 0; jj < 16; ++jj)
#pragma unroll
        for (int iq = 0; iq < 8; ++iq)
            acc[iq] = fmaf(w[iq - jj + 16], pj[jj], acc[iq]);
}

// history matvec, J ASCENDING (oldest tile first, freshest last).
// Unit J: window wrow + 16*(CNT-1-J), pred tile J.
// Tile 0 comes from the persistent register cache pj0 (no LDS).
template<int CNT>
__device__ __forceinline__ void histmac(float* acc, const float* wrow,
                                        const float* predRow, const float* pj0) {
    {   // J = 0: register-cached tile
        float w[24]; load24(w, wrow + 16 * (CNT - 1));
        mac8x16(acc, w, pj0);
    }
#pragma unroll
    for (int J = 1; J < CNT; ++J) {
        float w[24];  load24(w,  wrow + 16 * (CNT - 1 - J));
        float pj[16]; load16(pj, predRow + 16 * J);
        mac8x16(acc, w, pj);
    }
}
__device__ __forceinline__ void hist_dispatch(int n, float* acc,
                                              const float* wrow,
                                              const float* predRow,
                                              const float* pj0) {
    switch (n) {
        case 1: histmac<1>(acc, wrow, predRow, pj0); break;
        case 2: histmac<2>(acc, wrow, predRow, pj0); break;
        case 3: histmac<3>(acc, wrow, predRow, pj0); break;
        case 4: histmac<4>(acc, wrow, predRow, pj0); break;
        case 5: histmac<5>(acc, wrow, predRow, pj0); break;
        case 6: histmac<6>(acc, wrow, predRow, pj0); break;
        case 7: histmac<7>(acc, wrow, predRow, pj0); break;
        default: break;
    }
}

__global__ void __launch_bounds__(TPB, 1) npi_fused(
    const float* __restrict__ rt,
    const float* __restrict__ gt,
    const float* __restrict__ SI,
    const float* __restrict__ f,
    const float* __restrict__ seed,
    float* __restrict__ out)
{
    extern __shared__ float sm[];
    float* sSI   = sm;                 // [PAD]
    float* sPred = sm + PAD;           // [RPB][PAD]
    float* sF    = sPred + RPB * PAD;  // [RPB][PAD] f_eff rows

    const int tid = threadIdx.x;
    const int g   = tid >> 7;          // role: 0=P0,1=P1,2=C0,3=C1
    const int rid = tid & (RPB - 1);
    const int h8  = (g & 1) ? 8 : 0;   // half offset within tile
    const int m   = blockIdx.x * RPB + rid;

    float* myPred = sPred + rid * PAD;
    float* myF    = sF + rid * PAD;

    // ---- staging: f coalesced by all roles, SI ------------------------------
    {
        const int k0 = g * 32;
#pragma unroll 8
        for (int k = k0; k < k0 + 32; ++k)
            myF[k] = (k < 2) ? 0.0f : f[k * MREG + m];   // f_eff
    }
    if (tid < N2) sSI[tid] = SI[tid];
    else if (tid < PAD) sSI[tid] = 0.0f;
    __syncthreads();

    float siL[T];          // producers
    float fL[T];           // consumers
    float loss = 0.f;

    if (g <= 1) {
#pragma unroll
        for (int d = 1; d < T; ++d) siL[d] = sSI[d];
    } else {
#pragma unroll
        for (int d = 2; d < T; ++d) fL[d] = myF[d];
    }

    // ---- tile 0: P0 computes full seed tile ---------------------------------
    if (g == 0) {
        float rtt[T];
#pragma unroll
        for (int ii = START; ii < T; ++ii) rtt[ii] = rt[ii * MREG + m];
        float pt[T], s[T];
#pragma unroll
        for (int ii = 0; ii < START; ++ii) pt[ii] = seed[ii * MREG + m];
#pragma unroll
        for (int ii = START; ii < T; ++ii) s[ii] = 0.f;
#pragma unroll
        for (int jj = 0; jj < T; ++jj) {
            if (jj >= START) pt[jj] = rtt[jj] * s[jj];
#pragma unroll
            for (int ii = (jj + 1 > START ? jj + 1 : START); ii < T; ++ii)
                s[ii] = fmaf(siL[ii - jj], pt[jj], s[ii]);
        }
#pragma unroll
        for (int q = 0; q < 4; ++q)
            *reinterpret_cast<float4*>(myPred + 4*q) =
                make_float4(pt[4*q], pt[4*q+1], pt[4*q+2], pt[4*q+3]);
    }
    __syncthreads();

    // ---- persistent register cache of pred tile 0 ---------------------------
    float pj0[T];
    load16(pj0, myPred);

    // ---- pipelined phases: producers build tile I, consumers eat tile I-1 --
#pragma unroll 1
    for (int I = 1; I <= NT; ++I) {
        if (g < 2) {
            if (I < NT) {
                const int c = I * T;
                float rtt[8];
#pragma unroll
                for (int q = 0; q < 8; ++q)
                    rtt[q] = rt[(c + h8 + q) * MREG + m];

                float acc[8] = {0,0,0,0,0,0,0,0};
                hist_dispatch(I, acc, sSI + h8, myPred, pj0);

                if (g == 0) {
                    float pt[8];
#pragma unroll
                    for (int jj = 0; jj < 8; ++jj) {
                        pt[jj] = rtt[jj] * acc[jj];
#pragma unroll
                        for (int iq = jj + 1; iq < 8; ++iq)
                            acc[iq] = fmaf(siL[iq - jj], pt[jj], acc[iq]);
                    }
#pragma unroll
                    for (int q = 0; q < 2; ++q)
                        *reinterpret_cast<float4*>(myPred + c + 4*q) =
                            make_float4(pt[4*q], pt[4*q+1], pt[4*q+2], pt[4*q+3]);
                }

                // producer-only handoff barrier (threads 0..255)
                asm volatile("bar.sync 1, 256;" ::: "memory");

                if (g == 1) {
                    float ptL[8];
#pragma unroll
                    for (int q = 0; q < 2; ++q)
                        *reinterpret_cast<float4*>(ptL + 4*q) =
                            *reinterpret_cast<const float4*>(myPred + c + 4*q);
#pragma unroll
                    for (int jj = 0; jj < 8; ++jj)
#pragma unroll
                        for (int iq = 0; iq < 8; ++iq)
                            acc[iq] = fmaf(siL[iq + 8 - jj], ptL[jj], acc[iq]);
                    float pt[8];
#pragma unroll
                    for (int jj = 0; jj < 8; ++jj) {
                        pt[jj] = rtt[jj] * acc[jj];
#pragma unroll
                        for (int iq = jj + 1; iq < 8; ++iq)
                            acc[iq] = fmaf(siL[iq - jj], pt[jj], acc[iq]);
                    }
#pragma unroll
                    for (int q = 0; q < 2; ++q)
                        *reinterpret_cast<float4*>(myPred + c + 8 + 4*q) =
                            make_float4(pt[4*q], pt[4*q+1], pt[4*q+2], pt[4*q+3]);
                }
            }
        } else {
            // consumers: full output tile IC = I-1
            const int IC = I - 1;
            const int c2 = IC * T;
            float gtt[8];
#pragma unroll
            for (int q = 0; q < 8; ++q)
                gtt[q] = gt[(c2 + h8 + q) * MREG + m];

            float dacc[8] = {0,0,0,0,0,0,0,0};
            if (IC >= 1)
                hist_dispatch(IC, dacc, myF + h8, myPred, pj0);

            // diagonal tile: lags >= 2 within tile IC (freshest tile, read last)
            float pdl[T];
            const float* pd;
            if (IC == 0) {
                pd = pj0;
            } else {
                load16(pdl, myPred + c2);
                pd = pdl;
            }
            if (h8 == 0) {
#pragma unroll
                for (int jj = 0; jj < T; ++jj)
#pragma unroll
                    for (int iq = 0; iq < 8; ++iq)
                        if (iq - jj >= 2)
                            dacc[iq] = fmaf(fL[iq - jj], pd[jj], dacc[iq]);
            } else {
#pragma unroll
                for (int jj = 0; jj < T; ++jj)
#pragma unroll
                    for (int iq = 0; iq < 8; ++iq)
                        if (8 + iq - jj >= 2 && 8 + iq - jj <= 15)
                            dacc[iq] = fmaf(fL[8 + iq - jj], pd[jj], dacc[iq]);
            }

#pragma unroll
            for (int iq = 0; iq < 8; ++iq) {
                const int i = c2 + h8 + iq;
                float dp = dacc[iq];
                if (i < START) dp = (i == 0) ? 1e-9f : 0.f;
                const float diff = dp - gtt[iq];
                loss = fmaf(diff, diff, loss);
            }
        }
        __syncthreads();   // end of phase: tile I published
    }

    // ---- deterministic fused reduction --------------------------------------
#pragma unroll
    for (int o = 16; o; o >>= 1)
        loss += __shfl_xor_sync(0xffffffffu, loss, o);
    __shared__ float warpsum[TPB / 32];
    __shared__ bool  s_last;
    if ((tid & 31) == 0) warpsum[tid >> 5] = loss;
    __syncthreads();
    if (tid == 0) {
        float s = 0.f;
#pragma unroll
        for (int w = 0; w < TPB / 32; ++w) s += warpsum[w];
        g_partials[blockIdx.x] = s;
        __threadfence();
        unsigned prev = atomicAdd(&g_count, 1u);
        s_last = (prev == NBLK - 1u);
    }
    __syncthreads();
    if (s_last && tid < 32) {
        float v = 0.f;
#pragma unroll
        for (int k = 0; k < NBLK / 32; ++k)
            v += g_partials[tid + k * 32];
#pragma unroll
        for (int o = 16; o; o >>= 1)
            v += __shfl_xor_sync(0xffffffffu, v, o);
        if (tid == 0) {
            out[0] = v * (1.0f / ((float)N2 * (float)MREG));
            g_count = 0;   // reset for graph replay
        }
    }
}

extern "C" void kernel_launch(void* const* d_in, const int* in_sizes, int n_in,
                              void* d_out, int out_size)
{
    const float* rt   = (const float*)d_in[0];
    const float* gt   = (const float*)d_in[1];
    const float* SI   = (const float*)d_in[2];
    const float* f    = (const float*)d_in[3];
    const float* seed = (const float*)d_in[4];

    static bool attr_set = false;
    if (!attr_set) {
        cudaFuncSetAttribute(npi_fused,
                             cudaFuncAttributeMaxDynamicSharedMemorySize,
                             SMEM_BYTES);
        attr_set = true;
    }

    npi_fused<<<NBLK, TPB, SMEM_BYTES>>>(rt, gt, SI, f, seed, (float*)d_out);
}

// round 17
// speedup vs baseline: 1.4827x; 1.0664x over previous
#include <cuda_runtime.h>

#define N2    128
#define MREG  16384
#define START 6
#define RPB   128            // regions per block
#define TPB   512            // 4 roles x 128 regions
#define NBLK  (MREG / RPB)   // 128
#define T     16
#define NT    (N2 / T)       // 8
#define PAD   132

// smem floats: sSI[PAD] + sPred[RPB*PAD] + sF[RPB*PAD]
#define SMEM_FLOATS (PAD + 2 * RPB * PAD)
#define SMEM_BYTES  (SMEM_FLOATS * 4)

__device__ float        g_partials[NBLK];
__device__ unsigned int g_count = 0;

__device__ __forceinline__ void load16(float* d, const float* s) {
#pragma unroll
    for (int q = 0; q < 4; ++q)
        *reinterpret_cast<float4*>(d + 4*q) = *reinterpret_cast<const float4*>(s + 4*q);
}
__device__ __forceinline__ void load24(float* d, const float* s) {
#pragma unroll
    for (int q = 0; q < 6; ++q)
        *reinterpret_cast<float4*>(d + 4*q) = *reinterpret_cast<const float4*>(s + 4*q);
}
// acc[iq] += w[iq-jj+16] * pj[jj]
__device__ __forceinline__ void mac8x16(float* acc, const float* w, const float* pj) {
#pragma unroll
    for (int jj = 0; jj < 16; ++jj)
#pragma unroll
        for (int iq = 0; iq < 8; ++iq)
            acc[iq] = fmaf(w[iq - jj + 16], pj[jj], acc[iq]);
}

// fully-unrolled history matvec: CNT units, k ascending == J descending.
template<int CNT>
__device__ __forceinline__ void histmac(float* acc, const float* wrow,
                                        const float* predRow) {
#pragma unroll
    for (int k = 0; k < CNT; ++k) {
        float w[24];  load24(w,  wrow + 16 * k);
        float pj[16]; load16(pj, predRow + 16 * (CNT - 1 - k));
        mac8x16(acc, w, pj);
    }
}
__device__ __forceinline__ void hist_dispatch(int n, float* acc,
                                              const float* wrow,
                                              const float* predRow) {
    switch (n) {
        case 1: histmac<1>(acc, wrow, predRow); break;
        case 2: histmac<2>(acc, wrow, predRow); break;
        case 3: histmac<3>(acc, wrow, predRow); break;
        case 4: histmac<4>(acc, wrow, predRow); break;
        case 5: histmac<5>(acc, wrow, predRow); break;
        case 6: histmac<6>(acc, wrow, predRow); break;
        default: break;
    }
}

__global__ void __launch_bounds__(TPB, 1) npi_fused(
    const float* __restrict__ rt,
    const float* __restrict__ gt,
    const float* __restrict__ SI,
    const float* __restrict__ f,
    const float* __restrict__ seed,
    float* __restrict__ out)
{
    extern __shared__ float sm[];
    float* sSI   = sm;                 // [PAD]
    float* sPred = sm + PAD;           // [RPB][PAD]
    float* sF    = sPred + RPB * PAD;  // [RPB][PAD] f_eff rows

    const int tid = threadIdx.x;
    const int g   = tid >> 7;          // role: 0=P0,1=P1,2=C0,3=C1
    const int rid = tid & (RPB - 1);
    const int h8  = (g & 1) ? 8 : 0;   // half offset within tile
    const int m   = blockIdx.x * RPB + rid;

    float* myPred = sPred + rid * PAD;
    float* myF    = sF + rid * PAD;

    // ---- staging: f coalesced by all roles, SI ------------------------------
    {
        const int k0 = g * 32;
#pragma unroll 8
        for (int k = k0; k < k0 + 32; ++k)
            myF[k] = (k < 2) ? 0.0f : f[k * MREG + m];   // f_eff
    }
    if (tid < N2) sSI[tid] = SI[tid];
    else if (tid < PAD) sSI[tid] = 0.0f;
    __syncthreads();

    float siL[T];          // producers
    float fL[T];           // consumers
    float loss = 0.f;
    float dacc7[8] = {0,0,0,0,0,0,0,0};   // consumers: early tile-7 accumulator

    if (g <= 1) {
#pragma unroll
        for (int d = 1; d < T; ++d) siL[d] = sSI[d];
    } else {
#pragma unroll
        for (int d = 2; d < T; ++d) fL[d] = myF[d];
    }

    // ---- tile 0: P0 computes full seed tile ---------------------------------
    if (g == 0) {
        float rtt[T];
#pragma unroll
        for (int ii = START; ii < T; ++ii) rtt[ii] = rt[ii * MREG + m];
        float pt[T], s[T];
#pragma unroll
        for (int ii = 0; ii < START; ++ii) pt[ii] = seed[ii * MREG + m];
#pragma unroll
        for (int ii = START; ii < T; ++ii) s[ii] = 0.f;
#pragma unroll
        for (int jj = 0; jj < T; ++jj) {
            if (jj >= START) pt[jj] = rtt[jj] * s[jj];
#pragma unroll
            for (int ii = (jj + 1 > START ? jj + 1 : START); ii < T; ++ii)
                s[ii] = fmaf(siL[ii - jj], pt[jj], s[ii]);
        }
#pragma unroll
        for (int q = 0; q < 4; ++q)
            *reinterpret_cast<float4*>(myPred + 4*q) =
                make_float4(pt[4*q], pt[4*q+1], pt[4*q+2], pt[4*q+3]);
    }
    __syncthreads();

    // ---- pipelined phases: producers build tile I, consumers eat tile I-1 --
#pragma unroll 1
    for (int I = 1; I <= NT; ++I) {
        if (g < 2) {
            if (I < NT) {
                const int c = I * T;
                float rtt[8];
#pragma unroll
                for (int q = 0; q < 8; ++q)
                    rtt[q] = rt[(c + h8 + q) * MREG + m];

                float acc[8] = {0,0,0,0,0,0,0,0};
                switch (I) {   // full stage-1 history matvec (J descending)
                    case 1: histmac<1>(acc, sSI + h8, myPred); break;
                    case 2: histmac<2>(acc, sSI + h8, myPred); break;
                    case 3: histmac<3>(acc, sSI + h8, myPred); break;
                    case 4: histmac<4>(acc, sSI + h8, myPred); break;
                    case 5: histmac<5>(acc, sSI + h8, myPred); break;
                    case 6: histmac<6>(acc, sSI + h8, myPred); break;
                    case 7: histmac<7>(acc, sSI + h8, myPred); break;
                    default: break;
                }

                if (g == 0) {
                    float pt[8];
#pragma unroll
                    for (int jj = 0; jj < 8; ++jj) {
                        pt[jj] = rtt[jj] * acc[jj];
#pragma unroll
                        for (int iq = jj + 1; iq < 8; ++iq)
                            acc[iq] = fmaf(siL[iq - jj], pt[jj], acc[iq]);
                    }
#pragma unroll
                    for (int q = 0; q < 2; ++q)
                        *reinterpret_cast<float4*>(myPred + c + 4*q) =
                            make_float4(pt[4*q], pt[4*q+1], pt[4*q+2], pt[4*q+3]);
                }

                // producer-only handoff barrier (threads 0..255)
                asm volatile("bar.sync 1, 256;" ::: "memory");

                if (g == 1) {
                    float ptL[8];
#pragma unroll
                    for (int q = 0; q < 2; ++q)
                        *reinterpret_cast<float4*>(ptL + 4*q) =
                            *reinterpret_cast<const float4*>(myPred + c + 4*q);
#pragma unroll
                    for (int jj = 0; jj < 8; ++jj)
#pragma unroll
                        for (int iq = 0; iq < 8; ++iq)
                            acc[iq] = fmaf(siL[iq + 8 - jj], ptL[jj], acc[iq]);
                    float pt[8];
#pragma unroll
                    for (int jj = 0; jj < 8; ++jj) {
                        pt[jj] = rtt[jj] * acc[jj];
#pragma unroll
                        for (int iq = jj + 1; iq < 8; ++iq)
                            acc[iq] = fmaf(siL[iq - jj], pt[jj], acc[iq]);
                    }
#pragma unroll
                    for (int q = 0; q < 2; ++q)
                        *reinterpret_cast<float4*>(myPred + c + 8 + 4*q) =
                            make_float4(pt[4*q], pt[4*q+1], pt[4*q+2], pt[4*q+3]);
                }
            }
        } else {
            // ===== consumers =====
            // early tile-7 unit: (K=7, J=I-2) — pred tile I-2 is ready
            if (I >= 2) {
                const int J = I - 2;
                float w[24];  load24(w,  myF + h8 + 16 * (6 - J));
                float pj[16]; load16(pj, myPred + 16 * J);
                mac8x16(dacc7, w, pj);
            }

            // regular output tile IC = I-1
            const int IC = I - 1;
            const int c2 = IC * T;
            float gtt[8];
#pragma unroll
            for (int q = 0; q < 8; ++q)
                gtt[q] = gt[(c2 + h8 + q) * MREG + m];

            float dacc[8];
            if (IC == 7) {
                // all off-diag units already accumulated in dacc7 (J=0..6)
#pragma unroll
                for (int q = 0; q < 8; ++q) dacc[q] = dacc7[q];
            } else {
#pragma unroll
                for (int q = 0; q < 8; ++q) dacc[q] = 0.f;
                if (IC >= 1)
                    hist_dispatch(IC, dacc, myF + h8, myPred);
            }

            // diagonal tile: lags >= 2 within tile IC
            float pd[T];
            load16(pd, myPred + c2);
            if (h8 == 0) {
#pragma unroll
                for (int jj = 0; jj < T; ++jj)
#pragma unroll
                    for (int iq = 0; iq < 8; ++iq)
                        if (iq - jj >= 2)
                            dacc[iq] = fmaf(fL[iq - jj], pd[jj], dacc[iq]);
            } else {
#pragma unroll
                for (int jj = 0; jj < T; ++jj)
#pragma unroll
                    for (int iq = 0; iq < 8; ++iq)
                        if (8 + iq - jj >= 2 && 8 + iq - jj <= 15)
                            dacc[iq] = fmaf(fL[8 + iq - jj], pd[jj], dacc[iq]);
            }

#pragma unroll
            for (int iq = 0; iq < 8; ++iq) {
                const int i = c2 + h8 + iq;
                float dp = dacc[iq];
                if (i < START) dp = (i == 0) ? 1e-9f : 0.f;
                const float diff = dp - gtt[iq];
                loss = fmaf(diff, diff, loss);
            }
        }
        __syncthreads();   // end of phase: tile I published
    }

    // ---- deterministic fused reduction --------------------------------------
#pragma unroll
    for (int o = 16; o; o >>= 1)
        loss += __shfl_xor_sync(0xffffffffu, loss, o);
    __shared__ float warpsum[TPB / 32];
    __shared__ bool  s_last;
    if ((tid & 31) == 0) warpsum[tid >> 5] = loss;
    __syncthreads();
    if (tid == 0) {
        float s = 0.f;
#pragma unroll
        for (int w = 0; w < TPB / 32; ++w) s += warpsum[w];
        g_partials[blockIdx.x] = s;
        __threadfence();
        unsigned prev = atomicAdd(&g_count, 1u);
        s_last = (prev == NBLK - 1u);
    }
    __syncthreads();
    if (s_last && tid < 32) {
        float v = 0.f;
#pragma unroll
        for (int k = 0; k < NBLK / 32; ++k)
            v += g_partials[tid + k * 32];
#pragma unroll
        for (int o = 16; o; o >>= 1)
            v += __shfl_xor_sync(0xffffffffu, v, o);
        if (tid == 0) {
            out[0] = v * (1.0f / ((float)N2 * (float)MREG));
            g_count = 0;   // reset for graph replay
        }
    }
}

extern "C" void kernel_launch(void* const* d_in, const int* in_sizes, int n_in,
                              void* d_out, int out_size)
{
    const float* rt   = (const float*)d_in[0];
    const float* gt   = (const float*)d_in[1];
    const float* SI   = (const float*)d_in[2];
    const float* f    = (const float*)d_in[3];
    const float* seed = (const float*)d_in[4];

    static bool attr_set = false;
    if (!attr_set) {
        cudaFuncSetAttribute(npi_fused,
                             cudaFuncAttributeMaxDynamicSharedMemorySize,
                             SMEM_BYTES);
        attr_set = true;
    }

    npi_fused<<<NBLK, TPB, SMEM_BYTES>>>(rt, gt, SI, f, seed, (float*)d_out);
}